// round 1
// baseline (speedup 1.0000x reference)
#include <cuda_runtime.h>
#include <cstdint>

#define IM 1024
#define NSEG 128
#define EPSF 1e-10f
#define BLOCK 256
#define PPT 4   // pixels per thread along y

// Scratch for global min/max reduction (bit-ordered: all field sums are > 0,
// so unsigned-int compare == float compare).
__device__ unsigned g_min_bits;
__device__ unsigned g_max_bits;

__global__ void sk_init_kernel() {
    g_min_bits = 0x7F800000u;  // +inf
    g_max_bits = 0x00000000u;  // 0.0f (sums are strictly positive)
}

__global__ void __launch_bounds__(BLOCK)
sk_render_kernel(const float* __restrict__ xs, const float* __restrict__ ys,
                 float* __restrict__ out) {
    __shared__ float s_dx2[NSEG], s_dxdy[NSEG], s_c0[NSEG], s_invd[NSEG];
    __shared__ float s_a[NSEG], s_b[NSEG];
    __shared__ float s_xlo[NSEG], s_xhi[NSEG], s_ylo[NSEG], s_yhi[NSEG];
    __shared__ unsigned s_vert[NSEG];
    __shared__ float s_wmin[BLOCK / 32], s_wmax[BLOCK / 32];

    const int tid = threadIdx.x;

    if (tid < NSEG) {
        float x0 = xs[tid], x1 = xs[tid + 1];
        float y0 = ys[tid], y1 = ys[tid + 1];
        float dx = x1 - x0;
        float dy = y1 - y0;
        float dx2 = dx * dx;
        float cross = y0 * x1 - x0 * y1;   // y0*x1 - x0*y1
        s_dx2[tid]  = dx2;
        s_dxdy[tid] = dx * dy;
        s_c0[tid]   = -dy * cross;         // (y0-y1)*(y0*x1-x0*y1)
        s_invd[tid] = 1.0f / (dx2 + dy * dy + EPSF);
        float invdxe = 1.0f / (dx + EPSF);
        s_a[tid] = dy * invdxe;
        s_b[tid] = cross * invdxe;
        s_xlo[tid] = fminf(x0, x1);
        s_xhi[tid] = fmaxf(x0, x1);
        s_ylo[tid] = fminf(y0, y1);
        s_yhi[tid] = fmaxf(y0, y1);
        s_vert[tid] = (x0 == x1) ? 1u : 0u;
    }
    __syncthreads();

    // Block -> pixels: 4 blocks across x (256 cols each), 256 blocks across y
    // (PPT=4 rows each). Thread owns one x column, PPT consecutive rows.
    const int bx = blockIdx.x & 3;
    const int by = blockIdx.x >> 2;
    const int x  = bx * BLOCK + tid;
    const int y0i = by * PPT;
    const float xp = (float)x;

    float yp[PPT];
    float acc[PPT];
#pragma unroll
    for (int j = 0; j < PPT; j++) {
        yp[j]  = (float)(y0i + j);
        acc[j] = 0.0f;
    }

#pragma unroll 2
    for (int k = 0; k < NSEG; k++) {
        const float dx2  = s_dx2[k];
        const float dxdy = s_dxdy[k];
        const float c0   = s_c0[k];
        const float invd = s_invd[k];
        const float a    = s_a[k];
        const float b    = s_b[k];
        const float xlo  = s_xlo[k];
        const float xhi  = s_xhi[k];
        const float ylo  = s_ylo[k];
        const float yhi  = s_yhi[k];
        const bool vert  = (s_vert[k] != 0u);

        const float tmpx = fmaf(dx2, xp, c0);   // xp*dx2 + (y0-y1)*cross
#pragma unroll
        for (int j = 0; j < PPT; j++) {
            float n  = fmaf(dxdy, yp[j], tmpx);     // numerator
            float xg = n * invd;                    // x_gen (also correct-enough for vert: clamp fixes it)
            float yg = fmaf(a, xg, b);              // y_gen
            float ycp = vert ? yp[j] : yg;
            float xc = fminf(fmaxf(xg, xlo), xhi);
            float yc = fminf(fmaxf(ycp, ylo), yhi);
            float ex = xp - xc;
            float ey = yp[j] - yc;
            float d2 = fmaf(ex, ex, fmaf(ey, ey, EPSF));
            acc[j] = fmaf(d2, rsqrtf(d2), acc[j]);  // += sqrt(d2), FUZZ=1
        }
    }

    // Write sums + local min/max
    float lmin = acc[0], lmax = acc[0];
#pragma unroll
    for (int j = 0; j < PPT; j++) {
        out[(y0i + j) * IM + x] = acc[j];
        lmin = fminf(lmin, acc[j]);
        lmax = fmaxf(lmax, acc[j]);
    }

    // Warp reduce
#pragma unroll
    for (int off = 16; off > 0; off >>= 1) {
        lmin = fminf(lmin, __shfl_xor_sync(0xFFFFFFFFu, lmin, off));
        lmax = fmaxf(lmax, __shfl_xor_sync(0xFFFFFFFFu, lmax, off));
    }
    const int lane = tid & 31;
    const int warp = tid >> 5;
    if (lane == 0) { s_wmin[warp] = lmin; s_wmax[warp] = lmax; }
    __syncthreads();
    if (tid == 0) {
        float bmin = s_wmin[0], bmax = s_wmax[0];
#pragma unroll
        for (int w = 1; w < BLOCK / 32; w++) {
            bmin = fminf(bmin, s_wmin[w]);
            bmax = fmaxf(bmax, s_wmax[w]);
        }
        atomicMin(&g_min_bits, __float_as_uint(bmin));
        atomicMax(&g_max_bits, __float_as_uint(bmax));
    }
}

__global__ void __launch_bounds__(BLOCK)
sk_normalize_kernel(float* __restrict__ out) {
    const float tmin = __uint_as_float(g_min_bits);
    const float tmax = __uint_as_float(g_max_bits);
    const float s = 1.0f / (tmax - tmin);
    const int i = blockIdx.x * BLOCK + threadIdx.x;  // one float4 per thread
    float4* p = reinterpret_cast<float4*>(out) + i;
    float4 v = *p;
    v.x = (v.x - tmin) * s;
    v.y = (v.y - tmin) * s;
    v.z = (v.z - tmin) * s;
    v.w = (v.w - tmin) * s;
    *p = v;
}

extern "C" void kernel_launch(void* const* d_in, const int* in_sizes, int n_in,
                              void* d_out, int out_size) {
    const float* xs = (const float*)d_in[0];
    const float* ys = (const float*)d_in[1];
    float* out = (float*)d_out;

    sk_init_kernel<<<1, 1>>>();
    // 4 blocks in x (1024/256), 256 block-rows in y (1024/PPT)
    sk_render_kernel<<<(IM / BLOCK) * (IM / PPT), BLOCK>>>(xs, ys, out);
    // 1M floats / (4 per thread * 256 threads) = 1024 blocks
    sk_normalize_kernel<<<(IM * IM) / (4 * BLOCK), BLOCK>>>(out);
}

// round 2
// speedup vs baseline: 1.5845x; 1.5845x over previous
#include <cuda_runtime.h>
#include <cstdint>

#define IM 1024
#define NSEG 128
#define EPSF 1e-10f
#define BLOCK 128   // render block (== NSEG for easy setup)
#define PPT 8       // pixels per thread along y
#define NBLOCK 256  // normalize block

// Scratch for global min/max reduction (bit-ordered: all field sums are >= 0,
// so unsigned-int compare == float compare).
__device__ unsigned g_min_bits;
__device__ unsigned g_max_bits;

__global__ void sk_init_kernel() {
    g_min_bits = 0x7F800000u;  // +inf
    g_max_bits = 0x00000000u;  // 0.0f
}

__device__ __forceinline__ float fsqrt_approx(float x) {
    float r;
    asm("sqrt.approx.f32 %0, %1;" : "=f"(r) : "f"(x));
    return r;
}

__global__ void __launch_bounds__(BLOCK)
sk_render_kernel(const float* __restrict__ xs, const float* __restrict__ ys,
                 float* __restrict__ out) {
    // Per-segment constants: A = (nx0=-x0, ny0=-y0, dxi=dx*invd, dyi=dy*invd)
    //                        B = (ndx=-dx, ndy=-dy)
    __shared__ float4 sA[NSEG];
    __shared__ float2 sB[NSEG];
    __shared__ float s_wmin[BLOCK / 32], s_wmax[BLOCK / 32];

    const int tid = threadIdx.x;

    {
        float x0 = xs[tid], x1 = xs[tid + 1];
        float y0 = ys[tid], y1 = ys[tid + 1];
        float dx = x1 - x0;
        float dy = y1 - y0;
        float invd = 1.0f / (fmaf(dx, dx, dy * dy) + EPSF);
        sA[tid] = make_float4(-x0, -y0, dx * invd, dy * invd);
        sB[tid] = make_float2(-dx, -dy);
    }
    __syncthreads();

    // 8 blocks across x (128 cols each), 128 block-rows across y (PPT=8 rows).
    const int bx = blockIdx.x & 7;
    const int by = blockIdx.x >> 3;
    const int x  = bx * BLOCK + tid;
    const int y0i = by * PPT;
    const float xp = (float)x;

    float yp[PPT];
    float acc[PPT];
#pragma unroll
    for (int j = 0; j < PPT; j++) {
        yp[j]  = (float)(y0i + j);
        acc[j] = 0.0f;
    }

#pragma unroll 2
    for (int k = 0; k < NSEG; k++) {
        const float4 a = sA[k];
        const float2 b = sB[k];
        const float txk = xp + a.x;        // xp - x0
        const float qxi = txk * a.z;       // (xp-x0)*dx*invd

#pragma unroll
        for (int j = 0; j < PPT; j++) {
            float yd = yp[j] + a.y;                       // yp - y0
            float t  = __saturatef(fmaf(yd, a.w, qxi));   // clamp(t, 0, 1)
            float ex = fmaf(t, b.x, txk);                 // xp - (x0 + t*dx)
            float ey = fmaf(t, b.y, yd);                  // yp - (y0 + t*dy)
            float d2 = fmaf(ex, ex, fmaf(ey, ey, EPSF));
            acc[j] += fsqrt_approx(d2);
        }
    }

    // Write sums + local min/max
    float lmin = acc[0], lmax = acc[0];
#pragma unroll
    for (int j = 0; j < PPT; j++) {
        out[(y0i + j) * IM + x] = acc[j];
        lmin = fminf(lmin, acc[j]);
        lmax = fmaxf(lmax, acc[j]);
    }

    // Warp reduce
#pragma unroll
    for (int off = 16; off > 0; off >>= 1) {
        lmin = fminf(lmin, __shfl_xor_sync(0xFFFFFFFFu, lmin, off));
        lmax = fmaxf(lmax, __shfl_xor_sync(0xFFFFFFFFu, lmax, off));
    }
    const int lane = tid & 31;
    const int warp = tid >> 5;
    if (lane == 0) { s_wmin[warp] = lmin; s_wmax[warp] = lmax; }
    __syncthreads();
    if (tid == 0) {
        float bmin = s_wmin[0], bmax = s_wmax[0];
#pragma unroll
        for (int w = 1; w < BLOCK / 32; w++) {
            bmin = fminf(bmin, s_wmin[w]);
            bmax = fmaxf(bmax, s_wmax[w]);
        }
        atomicMin(&g_min_bits, __float_as_uint(bmin));
        atomicMax(&g_max_bits, __float_as_uint(bmax));
    }
}

__global__ void __launch_bounds__(NBLOCK)
sk_normalize_kernel(float* __restrict__ out) {
    const float tmin = __uint_as_float(g_min_bits);
    const float tmax = __uint_as_float(g_max_bits);
    const float s = 1.0f / (tmax - tmin);
    const int i = blockIdx.x * NBLOCK + threadIdx.x;  // one float4 per thread
    float4* p = reinterpret_cast<float4*>(out) + i;
    float4 v = *p;
    v.x = (v.x - tmin) * s;
    v.y = (v.y - tmin) * s;
    v.z = (v.z - tmin) * s;
    v.w = (v.w - tmin) * s;
    *p = v;
}

extern "C" void kernel_launch(void* const* d_in, const int* in_sizes, int n_in,
                              void* d_out, int out_size) {
    const float* xs = (const float*)d_in[0];
    const float* ys = (const float*)d_in[1];
    float* out = (float*)d_out;

    sk_init_kernel<<<1, 1>>>();
    // 8 blocks in x (1024/128), 128 block-rows in y (1024/PPT)
    sk_render_kernel<<<(IM / BLOCK) * (IM / PPT), BLOCK>>>(xs, ys, out);
    // 1M floats / (4 per thread * 256 threads) = 1024 blocks
    sk_normalize_kernel<<<(IM * IM) / (4 * NBLOCK), NBLOCK>>>(out);
}